// round 13
// baseline (speedup 1.0000x reference)
#include <cuda_runtime.h>
#include <cuda_fp16.h>
#include <cuda_bf16.h>

#define IN_F 100000
#define OUT_F 100000
#define BSZ 64

#define T_BLOCKS 1563   // ceil(IN_F/64) transpose tiles
#define MAX_E 1024      // smem edge cap per block (mean 512, sd 22.6)

// device-global scratch (allocation-free rule)
__device__ __half g_xT[(size_t)IN_F * BSZ];              // x transposed, fp16
__device__ __align__(16) int2 g_edge[1600000];           // {col<<7, value bits}
__device__ int    g_row_ptr[OUT_F + 1];

// ---------------------------------------------------------------------------
// prep kernel:
//   blocks [0, T_BLOCKS)   : transpose x -> g_xT (fp32 -> fp16)
//   blocks [T_BLOCKS, ...) : normalize indices -> packed edges + row_ptr
// ---------------------------------------------------------------------------
__global__ void prep_kernel(const float* __restrict__ x,
                            const void*  __restrict__ rows_p,
                            const void*  __restrict__ cols_p,
                            const float* __restrict__ values,
                            int nnz) {
    if (blockIdx.x < T_BLOCKS) {
        __shared__ float tile[64][65];
        const int c0 = blockIdx.x * 64;
        const int t  = threadIdx.x;
        const int f  = t & 15;
        const int g  = t >> 4;

#pragma unroll
        for (int p = 0; p < 4; p++) {
            int b = p * 16 + g;
            int c = c0 + 4 * f;
            if (c < IN_F) {
                float4 v = *(const float4*)&x[(size_t)b * IN_F + c];
                tile[4 * f + 0][b] = v.x;
                tile[4 * f + 1][b] = v.y;
                tile[4 * f + 2][b] = v.z;
                tile[4 * f + 3][b] = v.w;
            }
        }
        __syncthreads();
#pragma unroll
        for (int p = 0; p < 4; p++) {
            int cl = p * 16 + g;
            if (c0 + cl < IN_F) {
                __half2 h0 = __floats2half2_rn(tile[cl][4 * f + 0], tile[cl][4 * f + 1]);
                __half2 h1 = __floats2half2_rn(tile[cl][4 * f + 2], tile[cl][4 * f + 3]);
                uint2 pk;
                pk.x = *(unsigned*)&h0;
                pk.y = *(unsigned*)&h1;
                *(uint2*)&g_xT[(size_t)(c0 + cl) * BSZ + 4 * f] = pk;
            }
        }
    } else {
        __shared__ int s_is64;
        if (threadIdx.x == 0) {
            const int* c32 = (const int*)cols_p;
            int fl = 1;
#pragma unroll
            for (int i = 0; i < 8; i++)
                if (c32[2 * i + 1] != 0) fl = 0;
            s_is64 = fl;
        }
        __syncthreads();

        int e = (blockIdx.x - T_BLOCKS) * 256 + threadIdx.x;
        if (e < nnz) {
            int c, r, pr;
            if (s_is64) {
                c  = (int)((const long long*)cols_p)[e];
                r  = (int)((const long long*)rows_p)[e];
                pr = (e > 0) ? (int)((const long long*)rows_p)[e - 1] : -1;
            } else {
                c  = ((const int*)cols_p)[e];
                r  = ((const int*)rows_p)[e];
                pr = (e > 0) ? ((const int*)rows_p)[e - 1] : -1;
            }
            g_edge[e] = make_int2(c << 7, __float_as_int(values[e]));

            for (int o = pr + 1; o <= r; o++) g_row_ptr[o] = e;
            if (e == nnz - 1)
                for (int o = r + 1; o <= OUT_F; o++) g_row_ptr[o] = nnz;
        }
    }
}

// ---------------------------------------------------------------------------
// fused SpMM, strip-balanced: block stages its edges in smem; each warp takes
// an EQUAL strip of ceil(cnt/32) edges. Per strip: binary-search the row of
// the head edge, run the unroll-4 independent-gather loop to the segment end,
// flush via 2 smem atomicAdd/lane, advance. ~3 segments/warp. No per-edge
// masks, no imbalance tail.
// ---------------------------------------------------------------------------
__global__ __launch_bounds__(1024) void spmm_kernel(const float* __restrict__ bias,
                                                    float* __restrict__ out) {
    __shared__ float tile[32][65];   // [row-in-block][batch]
    __shared__ int   rp_s[33];
    __shared__ __align__(16) int2 es[MAX_E];
    const int t    = threadIdx.x;
    const int w    = t >> 5;
    const int lane = t & 31;
    const int o0   = blockIdx.x * 32;

    if (t < 33) rp_s[t] = g_row_ptr[o0 + t];
    {
        float* tp = &tile[0][0];
        for (int i = t; i < 32 * 65; i += 1024) tp[i] = 0.f;
    }
    __syncthreads();

    const int S   = rp_s[0];
    const int E   = rp_s[32];
    const int cnt = E - S;

    // stage block's edges into smem (coalesced int2 loads)
    for (int i = t; i < min(cnt, MAX_E); i += 1024)
        es[i] = g_edge[S + i];
    __syncthreads();

    const char* __restrict__ xb = (const char*)g_xT + lane * 4;

    if (cnt <= MAX_E) {
        const int L  = (cnt + 31) >> 5;     // strip length (equal per warp)
        int       k  = w * L;
        const int k1 = min(k + L, cnt);

        while (k < k1) {
            // row containing local edge k (5-step smem binary search)
            int lo = 0, hi = 32;
            while (lo < hi) {
                int m = (lo + hi) >> 1;
                if (rp_s[m + 1] - S <= k) lo = m + 1; else hi = m;
            }
            const int r  = lo;
            const int se = min(k1, rp_s[r + 1] - S);

            float2 a0 = make_float2(0.f, 0.f);
            float2 a1 = make_float2(0.f, 0.f);
            int kk = k;
            for (; kk + 3 < se; kk += 4) {
                int2 e0 = es[kk];
                int2 e1 = es[kk + 1];
                int2 e2 = es[kk + 2];
                int2 e3 = es[kk + 3];
                __half2 h0 = *(const __half2*)(xb + e0.x);
                __half2 h1 = *(const __half2*)(xb + e1.x);
                __half2 h2 = *(const __half2*)(xb + e2.x);
                __half2 h3 = *(const __half2*)(xb + e3.x);
                float2 f0 = __half22float2(h0);
                float2 f1 = __half22float2(h1);
                float2 f2 = __half22float2(h2);
                float2 f3 = __half22float2(h3);
                float v0 = __int_as_float(e0.y);
                float v1 = __int_as_float(e1.y);
                float v2 = __int_as_float(e2.y);
                float v3 = __int_as_float(e3.y);
                a0.x = fmaf(v0, f0.x, a0.x); a0.y = fmaf(v0, f0.y, a0.y);
                a1.x = fmaf(v1, f1.x, a1.x); a1.y = fmaf(v1, f1.y, a1.y);
                a0.x = fmaf(v2, f2.x, a0.x); a0.y = fmaf(v2, f2.y, a0.y);
                a1.x = fmaf(v3, f3.x, a1.x); a1.y = fmaf(v3, f3.y, a1.y);
            }
            for (; kk < se; kk++) {
                int2 ed = es[kk];
                float2 xv = __half22float2(*(const __half2*)(xb + ed.x));
                float v = __int_as_float(ed.y);
                a0.x = fmaf(v, xv.x, a0.x); a0.y = fmaf(v, xv.y, a0.y);
            }
            atomicAdd(&tile[r][2 * lane + 0], a0.x + a1.x);
            atomicAdd(&tile[r][2 * lane + 1], a0.y + a1.y);
            k = se;
        }
    } else {
        // fallback (vanishingly rare): warp per row, descriptors from gmem
        float2 a = make_float2(0.f, 0.f);
        for (int k = rp_s[w]; k < rp_s[w + 1]; k++) {
            int2 ed = g_edge[k];
            float2 xv = __half22float2(*(const __half2*)(xb + ed.x));
            float v = __int_as_float(ed.y);
            a.x = fmaf(v, xv.x, a.x); a.y = fmaf(v, xv.y, a.y);
        }
        tile[w][2 * lane + 0] = a.x;
        tile[w][2 * lane + 1] = a.y;
    }
    __syncthreads();

    // write phase: thread t -> batch b = t/16, outputs 2*(t%16), +1
    const int b  = t >> 4;
    const int jj = t & 15;
    const int og = o0 + 2 * jj;
    float2 bv = *(const float2*)&bias[og];
    float2 rr;
    rr.x = tile[2 * jj + 0][b] + bv.x;
    rr.y = tile[2 * jj + 1][b] + bv.y;
    *(float2*)&out[(size_t)b * OUT_F + og] = rr;
}

// ---------------------------------------------------------------------------
extern "C" void kernel_launch(void* const* d_in, const int* in_sizes, int n_in,
                              void* d_out, int out_size) {
    const float* x      = (const float*)d_in[0];
    const float* values = (const float*)d_in[1];
    const float* bias   = (const float*)d_in[2];
    const void*  rows   = d_in[3];
    const void*  cols   = d_in[4];
    float* out = (float*)d_out;

    const int nnz      = in_sizes[1];
    const int e_blocks = (nnz + 255) / 256;

    // 1) fused: x transpose (fp32->fp16) + edge packing + row_ptr scatter
    prep_kernel<<<T_BLOCKS + e_blocks, 256>>>(x, rows, cols, values, nnz);

    // 2) strip-balanced fused gather/accumulate + bias + final write
    spmm_kernel<<<OUT_F / 32, 1024>>>(bias, out);
}

// round 14
// speedup vs baseline: 2.2575x; 2.2575x over previous
#include <cuda_runtime.h>
#include <cuda_fp16.h>
#include <cuda_bf16.h>

#define IN_F 100000
#define OUT_F 100000
#define BSZ 64

#define T_BLOCKS 1563     // ceil(IN_F/64) transpose tiles
#define ROWS_PB 96        // output rows per spmm block
#define SPMM_BLOCKS ((OUT_F + ROWS_PB - 1) / ROWS_PB)   // 1042
#define MAX_E 2048        // smem edge cap (mean 1536, sd 39 -> +13 sigma)

// device-global scratch (allocation-free rule)
__device__ __half g_xT[(size_t)IN_F * BSZ];   // x transposed, fp16: [IN_F][64]
__device__ int    g_row_ptr[OUT_F + 1];

// ---------------------------------------------------------------------------
// prep kernel:
//   blocks [0, T_BLOCKS)   : transpose x -> g_xT (fp32 -> fp16)
//   blocks [T_BLOCKS, ...) : row_ptr scatter (handles int32/int64 rows)
// ---------------------------------------------------------------------------
__global__ void prep_kernel(const float* __restrict__ x,
                            const void*  __restrict__ rows_p,
                            const int*   __restrict__ cols32,
                            int nnz) {
    if (blockIdx.x < T_BLOCKS) {
        __shared__ float tile[64][65];
        const int c0 = blockIdx.x * 64;
        const int t  = threadIdx.x;
        const int f  = t & 15;
        const int g  = t >> 4;

#pragma unroll
        for (int p = 0; p < 4; p++) {
            int b = p * 16 + g;
            int c = c0 + 4 * f;
            if (c < IN_F) {
                float4 v = *(const float4*)&x[(size_t)b * IN_F + c];
                tile[4 * f + 0][b] = v.x;
                tile[4 * f + 1][b] = v.y;
                tile[4 * f + 2][b] = v.z;
                tile[4 * f + 3][b] = v.w;
            }
        }
        __syncthreads();
#pragma unroll
        for (int p = 0; p < 4; p++) {
            int cl = p * 16 + g;
            if (c0 + cl < IN_F) {
                __half2 h0 = __floats2half2_rn(tile[cl][4 * f + 0], tile[cl][4 * f + 1]);
                __half2 h1 = __floats2half2_rn(tile[cl][4 * f + 2], tile[cl][4 * f + 3]);
                uint2 pk;
                pk.x = *(unsigned*)&h0;
                pk.y = *(unsigned*)&h1;
                *(uint2*)&g_xT[(size_t)(c0 + cl) * BSZ + 4 * f] = pk;
            }
        }
    } else {
        // index-width detection: cols uniform in [0,1e5); int64 => odd words 0
        __shared__ int s_is64;
        if (threadIdx.x == 0) {
            int fl = 1;
#pragma unroll
            for (int i = 0; i < 8; i++)
                if (cols32[2 * i + 1] != 0) fl = 0;
            s_is64 = fl;
        }
        __syncthreads();

        int e = (blockIdx.x - T_BLOCKS) * 256 + threadIdx.x;
        if (e < nnz) {
            int r, pr;
            if (s_is64) {
                r  = (int)((const long long*)rows_p)[e];
                pr = (e > 0) ? (int)((const long long*)rows_p)[e - 1] : -1;
            } else {
                r  = ((const int*)rows_p)[e];
                pr = (e > 0) ? ((const int*)rows_p)[e - 1] : -1;
            }
            // lower_bound semantics: row_ptr[o] = first edge with rows >= o
            for (int o = pr + 1; o <= r; o++) g_row_ptr[o] = e;
            if (e == nnz - 1)
                for (int o = r + 1; o <= OUT_F; o++) g_row_ptr[o] = nnz;
        }
    }
}

// ---------------------------------------------------------------------------
// fused SpMM: block owns 96 rows; stages its ~1536 edge descriptors into smem
// straight from cols/values (packing col<<7). Warp w owns rows w, w+32, w+64
// exclusively (no atomics, no zero-init). R12 unroll-4 independent-gather
// inner loop. Coalesced bias+write at the end.
// ---------------------------------------------------------------------------
__global__ __launch_bounds__(1024) void spmm_kernel(const void*  __restrict__ cols_p,
                                                    const float* __restrict__ values,
                                                    const float* __restrict__ bias,
                                                    float* __restrict__ out) {
    __shared__ float tile[ROWS_PB][65];    // [row-in-block][batch]
    __shared__ int   rp_s[ROWS_PB + 1];
    __shared__ __align__(16) int2 es[MAX_E];
    __shared__ int   s_is64;

    const int t    = threadIdx.x;
    const int w    = t >> 5;
    const int lane = t & 31;
    const int o0   = blockIdx.x * ROWS_PB;

    if (t == 0) {
        const int* c32 = (const int*)cols_p;
        int fl = 1;
#pragma unroll
        for (int i = 0; i < 8; i++)
            if (c32[2 * i + 1] != 0) fl = 0;
        s_is64 = fl;
    }
    for (int i = t; i <= ROWS_PB; i += 1024)
        rp_s[i] = g_row_ptr[min(o0 + i, OUT_F)];
    __syncthreads();

    const int S    = rp_s[0];
    const int E    = rp_s[ROWS_PB];
    const int cnt  = E - S;
    const int is64 = s_is64;

    // stage packed descriptors from cols/values (coalesced)
    const int cc = min(cnt, MAX_E);
    if (is64) {
        const long long* __restrict__ cols = (const long long*)cols_p;
        for (int i = t; i < cc; i += 1024)
            es[i] = make_int2(((int)cols[S + i]) << 7, __float_as_int(values[S + i]));
    } else {
        const int* __restrict__ cols = (const int*)cols_p;
        for (int i = t; i < cc; i += 1024)
            es[i] = make_int2(cols[S + i] << 7, __float_as_int(values[S + i]));
    }
    __syncthreads();

    const char* __restrict__ xb = (const char*)g_xT + lane * 4;

    if (cnt <= MAX_E) {
#pragma unroll
        for (int rr = 0; rr < 3; rr++) {
            const int r     = w + rr * 32;
            const int s_loc = rp_s[r] - S;
            const int e_loc = rp_s[r + 1] - S;

            float2 a0 = make_float2(0.f, 0.f);
            float2 a1 = make_float2(0.f, 0.f);
            int k = s_loc;
            for (; k + 3 < e_loc; k += 4) {
                int2 e0 = es[k];
                int2 e1 = es[k + 1];
                int2 e2 = es[k + 2];
                int2 e3 = es[k + 3];
                __half2 h0 = *(const __half2*)(xb + e0.x);
                __half2 h1 = *(const __half2*)(xb + e1.x);
                __half2 h2 = *(const __half2*)(xb + e2.x);
                __half2 h3 = *(const __half2*)(xb + e3.x);
                float2 f0 = __half22float2(h0);
                float2 f1 = __half22float2(h1);
                float2 f2 = __half22float2(h2);
                float2 f3 = __half22float2(h3);
                float v0 = __int_as_float(e0.y);
                float v1 = __int_as_float(e1.y);
                float v2 = __int_as_float(e2.y);
                float v3 = __int_as_float(e3.y);
                a0.x = fmaf(v0, f0.x, a0.x); a0.y = fmaf(v0, f0.y, a0.y);
                a1.x = fmaf(v1, f1.x, a1.x); a1.y = fmaf(v1, f1.y, a1.y);
                a0.x = fmaf(v2, f2.x, a0.x); a0.y = fmaf(v2, f2.y, a0.y);
                a1.x = fmaf(v3, f3.x, a1.x); a1.y = fmaf(v3, f3.y, a1.y);
            }
            for (; k < e_loc; k++) {
                int2 ed = es[k];
                float2 xv = __half22float2(*(const __half2*)(xb + ed.x));
                float v = __int_as_float(ed.y);
                a0.x = fmaf(v, xv.x, a0.x); a0.y = fmaf(v, xv.y, a0.y);
            }
            tile[r][2 * lane + 0] = a0.x + a1.x;
            tile[r][2 * lane + 1] = a0.y + a1.y;
        }
    } else {
        // fallback (vanishingly rare): descriptors straight from gmem
#pragma unroll
        for (int rr = 0; rr < 3; rr++) {
            const int r = w + rr * 32;
            float2 a = make_float2(0.f, 0.f);
            if (is64) {
                const long long* __restrict__ cols = (const long long*)cols_p;
                for (int k = rp_s[r]; k < rp_s[r + 1]; k++) {
                    int coff = ((int)cols[k]) << 7;
                    float2 xv = __half22float2(*(const __half2*)(xb + coff));
                    float v = values[k];
                    a.x = fmaf(v, xv.x, a.x); a.y = fmaf(v, xv.y, a.y);
                }
            } else {
                const int* __restrict__ cols = (const int*)cols_p;
                for (int k = rp_s[r]; k < rp_s[r + 1]; k++) {
                    int coff = cols[k] << 7;
                    float2 xv = __half22float2(*(const __half2*)(xb + coff));
                    float v = values[k];
                    a.x = fmaf(v, xv.x, a.x); a.y = fmaf(v, xv.y, a.y);
                }
            }
            tile[r][2 * lane + 0] = a.x;
            tile[r][2 * lane + 1] = a.y;
        }
    }
    __syncthreads();

    // write phase: thread t -> batch b = t/16, jj = t%16;
    // 3 float2 stores per thread at rows 32p + 2jj
    const int b  = t >> 4;
    const int jj = t & 15;
#pragma unroll
    for (int p = 0; p < 3; p++) {
        const int rloc = 32 * p + 2 * jj;
        const int og   = o0 + rloc;
        if (og < OUT_F) {
            float2 bv = *(const float2*)&bias[og];
            float2 rv;
            rv.x = tile[rloc + 0][b] + bv.x;
            rv.y = tile[rloc + 1][b] + bv.y;
            *(float2*)&out[(size_t)b * OUT_F + og] = rv;
        }
    }
}

// ---------------------------------------------------------------------------
extern "C" void kernel_launch(void* const* d_in, const int* in_sizes, int n_in,
                              void* d_out, int out_size) {
    const float* x      = (const float*)d_in[0];
    const float* values = (const float*)d_in[1];
    const float* bias   = (const float*)d_in[2];
    const void*  rows   = d_in[3];
    const void*  cols   = d_in[4];
    float* out = (float*)d_out;

    const int nnz      = in_sizes[1];
    const int e_blocks = (nnz + 255) / 256;

    // 1) fused: x transpose (fp32->fp16) + row_ptr scatter
    prep_kernel<<<T_BLOCKS + e_blocks, 256>>>(x, rows, (const int*)cols, nnz);

    // 2) fused gather/accumulate + bias + final write (96 rows/block)
    spmm_kernel<<<SPMM_BLOCKS, 1024>>>(cols, values, bias, out);
}

// round 15
// speedup vs baseline: 2.4624x; 1.0907x over previous
#include <cuda_runtime.h>
#include <cuda_fp16.h>
#include <cuda_bf16.h>

#define IN_F 100000
#define OUT_F 100000
#define BSZ 64

#define T_BLOCKS 1563     // ceil(IN_F/64) transpose tiles
#define ROWS_PB 192       // output rows per spmm block
#define SPMM_BLOCKS ((OUT_F + ROWS_PB - 1) / ROWS_PB)   // 521
#define MAX_E 3584        // smem edge cap (mean 3072, sd ~55 -> +9 sigma)

// dynamic smem layout (bytes)
#define TILE_BYTES (ROWS_PB * 65 * 4)            // 49920
#define RP_BYTES   (((ROWS_PB + 1) * 4 + 15) & ~15)  // 784
#define ES_OFF     (TILE_BYTES + RP_BYTES)       // 50704 (16B aligned)
#define SMEM_TOTAL (ES_OFF + MAX_E * 8)          // 79376

// device-global scratch (allocation-free rule)
__device__ __half g_xT[(size_t)IN_F * BSZ];   // x transposed, fp16: [IN_F][64]
__device__ int    g_row_ptr[OUT_F + 1];

// ---------------------------------------------------------------------------
// prep kernel:
//   blocks [0, T_BLOCKS)   : transpose x -> g_xT (fp32 -> fp16)
//   blocks [T_BLOCKS, ...) : row_ptr scatter (handles int32/int64 rows)
// ---------------------------------------------------------------------------
__global__ void prep_kernel(const float* __restrict__ x,
                            const void*  __restrict__ rows_p,
                            const int*   __restrict__ cols32,
                            int nnz) {
    if (blockIdx.x < T_BLOCKS) {
        __shared__ float tile[64][65];
        const int c0 = blockIdx.x * 64;
        const int t  = threadIdx.x;
        const int f  = t & 15;
        const int g  = t >> 4;

#pragma unroll
        for (int p = 0; p < 4; p++) {
            int b = p * 16 + g;
            int c = c0 + 4 * f;
            if (c < IN_F) {
                float4 v = *(const float4*)&x[(size_t)b * IN_F + c];
                tile[4 * f + 0][b] = v.x;
                tile[4 * f + 1][b] = v.y;
                tile[4 * f + 2][b] = v.z;
                tile[4 * f + 3][b] = v.w;
            }
        }
        __syncthreads();
#pragma unroll
        for (int p = 0; p < 4; p++) {
            int cl = p * 16 + g;
            if (c0 + cl < IN_F) {
                __half2 h0 = __floats2half2_rn(tile[cl][4 * f + 0], tile[cl][4 * f + 1]);
                __half2 h1 = __floats2half2_rn(tile[cl][4 * f + 2], tile[cl][4 * f + 3]);
                uint2 pk;
                pk.x = *(unsigned*)&h0;
                pk.y = *(unsigned*)&h1;
                *(uint2*)&g_xT[(size_t)(c0 + cl) * BSZ + 4 * f] = pk;
            }
        }
    } else {
        // index-width detection: cols uniform in [0,1e5); int64 => odd words 0
        __shared__ int s_is64;
        if (threadIdx.x == 0) {
            int fl = 1;
#pragma unroll
            for (int i = 0; i < 8; i++)
                if (cols32[2 * i + 1] != 0) fl = 0;
            s_is64 = fl;
        }
        __syncthreads();

        int e = (blockIdx.x - T_BLOCKS) * 256 + threadIdx.x;
        if (e < nnz) {
            int r, pr;
            if (s_is64) {
                r  = (int)((const long long*)rows_p)[e];
                pr = (e > 0) ? (int)((const long long*)rows_p)[e - 1] : -1;
            } else {
                r  = ((const int*)rows_p)[e];
                pr = (e > 0) ? ((const int*)rows_p)[e - 1] : -1;
            }
            // lower_bound semantics: row_ptr[o] = first edge with rows >= o
            for (int o = pr + 1; o <= r; o++) g_row_ptr[o] = e;
            if (e == nnz - 1)
                for (int o = r + 1; o <= OUT_F; o++) g_row_ptr[o] = nnz;
        }
    }
}

// ---------------------------------------------------------------------------
// fused SpMM: block owns 192 rows (dynamic smem). Edge window rounded to even
// (S0) so cols/values stage as aligned pairs (LDG.128/LDG.64 + STS.128).
// Warp w owns rows w, w+32, ..., w+160 exclusively. Inner loop: int4 paired
// descriptors + 4 independent gathers. Coalesced bias+write at the end.
// ---------------------------------------------------------------------------
__global__ __launch_bounds__(1024, 2) void spmm_kernel(const void*  __restrict__ cols_p,
                                                       const float* __restrict__ values,
                                                       const float* __restrict__ bias,
                                                       float* __restrict__ out,
                                                       int nnz) {
    extern __shared__ __align__(16) char smem_raw[];
    float (*tile)[65] = (float (*)[65])smem_raw;
    int*  rp_s = (int*)(smem_raw + TILE_BYTES);
    int2* es   = (int2*)(smem_raw + ES_OFF);
    __shared__ int s_is64;

    const int t    = threadIdx.x;
    const int w    = t >> 5;
    const int lane = t & 31;
    const int o0   = blockIdx.x * ROWS_PB;

    if (t == 0) {
        const int* c32 = (const int*)cols_p;
        int fl = 1;
#pragma unroll
        for (int i = 0; i < 8; i++)
            if (c32[2 * i + 1] != 0) fl = 0;
        s_is64 = fl;
    }
    for (int i = t; i <= ROWS_PB; i += 1024)
        rp_s[i] = g_row_ptr[min(o0 + i, OUT_F)];
    __syncthreads();

    const int S    = rp_s[0];
    const int E    = rp_s[ROWS_PB];
    const int S0   = S & ~1;          // even base -> aligned pair staging
    const int cnt  = E - S0;
    const int is64 = s_is64;

    // stage packed descriptors {col<<7, value bits} as aligned pairs
    if (cnt <= MAX_E) {
        const int npair = cnt >> 1;
        if (is64) {
            const longlong2* __restrict__ cp = (const longlong2*)((const long long*)cols_p + S0);
            const float2*    __restrict__ vp = (const float2*)(values + S0);
            for (int i = t; i < npair; i += 1024) {
                longlong2 c = cp[i];
                float2    v = vp[i];
                ((int4*)es)[i] = make_int4(((int)c.x) << 7, __float_as_int(v.x),
                                           ((int)c.y) << 7, __float_as_int(v.y));
            }
        } else {
            const int2*   __restrict__ cp = (const int2*)((const int*)cols_p + S0);
            const float2* __restrict__ vp = (const float2*)(values + S0);
            for (int i = t; i < npair; i += 1024) {
                int2   c = cp[i];
                float2 v = vp[i];
                ((int4*)es)[i] = make_int4(c.x << 7, __float_as_int(v.x),
                                           c.y << 7, __float_as_int(v.y));
            }
        }
        if ((cnt & 1) && t == 0) {
            int e = S0 + cnt - 1;
            int c = is64 ? (int)((const long long*)cols_p)[e] : ((const int*)cols_p)[e];
            es[cnt - 1] = make_int2(c << 7, __float_as_int(values[e]));
        }
    }
    __syncthreads();

    const char* __restrict__ xb = (const char*)g_xT + lane * 4;

    if (cnt <= MAX_E) {
#pragma unroll
        for (int rr = 0; rr < ROWS_PB / 32; rr++) {
            const int r = w + rr * 32;
            int       k = rp_s[r] - S0;
            const int e_loc = rp_s[r + 1] - S0;

            float2 a0 = make_float2(0.f, 0.f);
            float2 a1 = make_float2(0.f, 0.f);

            // head: align k to even for int4 descriptor pairs
            if (k < e_loc && (k & 1)) {
                int2 ed = es[k];
                float2 xv = __half22float2(*(const __half2*)(xb + ed.x));
                float v = __int_as_float(ed.y);
                a0.x = fmaf(v, xv.x, a0.x); a0.y = fmaf(v, xv.y, a0.y);
                k++;
            }
            for (; k + 3 < e_loc; k += 4) {
                int4 d0 = *(const int4*)&es[k];
                int4 d1 = *(const int4*)&es[k + 2];
                __half2 h0 = *(const __half2*)(xb + d0.x);
                __half2 h1 = *(const __half2*)(xb + d0.z);
                __half2 h2 = *(const __half2*)(xb + d1.x);
                __half2 h3 = *(const __half2*)(xb + d1.z);
                float2 f0 = __half22float2(h0);
                float2 f1 = __half22float2(h1);
                float2 f2 = __half22float2(h2);
                float2 f3 = __half22float2(h3);
                float v0 = __int_as_float(d0.y);
                float v1 = __int_as_float(d0.w);
                float v2 = __int_as_float(d1.y);
                float v3 = __int_as_float(d1.w);
                a0.x = fmaf(v0, f0.x, a0.x); a0.y = fmaf(v0, f0.y, a0.y);
                a1.x = fmaf(v1, f1.x, a1.x); a1.y = fmaf(v1, f1.y, a1.y);
                a0.x = fmaf(v2, f2.x, a0.x); a0.y = fmaf(v2, f2.y, a0.y);
                a1.x = fmaf(v3, f3.x, a1.x); a1.y = fmaf(v3, f3.y, a1.y);
            }
            if (k + 1 < e_loc) {   // remaining aligned pair
                int4 d0 = *(const int4*)&es[k];
                __half2 h0 = *(const __half2*)(xb + d0.x);
                __half2 h1 = *(const __half2*)(xb + d0.z);
                float2 f0 = __half22float2(h0);
                float2 f1 = __half22float2(h1);
                float v0 = __int_as_float(d0.y);
                float v1 = __int_as_float(d0.w);
                a0.x = fmaf(v0, f0.x, a0.x); a0.y = fmaf(v0, f0.y, a0.y);
                a1.x = fmaf(v1, f1.x, a1.x); a1.y = fmaf(v1, f1.y, a1.y);
                k += 2;
            }
            if (k < e_loc) {       // scalar tail
                int2 ed = es[k];
                float2 xv = __half22float2(*(const __half2*)(xb + ed.x));
                float v = __int_as_float(ed.y);
                a0.x = fmaf(v, xv.x, a0.x); a0.y = fmaf(v, xv.y, a0.y);
            }
            tile[r][2 * lane + 0] = a0.x + a1.x;
            tile[r][2 * lane + 1] = a0.y + a1.y;
        }
    } else {
        // fallback (vanishingly rare): descriptors straight from gmem
#pragma unroll
        for (int rr = 0; rr < ROWS_PB / 32; rr++) {
            const int r = w + rr * 32;
            float2 a = make_float2(0.f, 0.f);
            if (is64) {
                const long long* __restrict__ cols = (const long long*)cols_p;
                for (int k = rp_s[r]; k < rp_s[r + 1]; k++) {
                    int coff = ((int)cols[k]) << 7;
                    float2 xv = __half22float2(*(const __half2*)(xb + coff));
                    float v = values[k];
                    a.x = fmaf(v, xv.x, a.x); a.y = fmaf(v, xv.y, a.y);
                }
            } else {
                const int* __restrict__ cols = (const int*)cols_p;
                for (int k = rp_s[r]; k < rp_s[r + 1]; k++) {
                    int coff = cols[k] << 7;
                    float2 xv = __half22float2(*(const __half2*)(xb + coff));
                    float v = values[k];
                    a.x = fmaf(v, xv.x, a.x); a.y = fmaf(v, xv.y, a.y);
                }
            }
            tile[r][2 * lane + 0] = a.x;
            tile[r][2 * lane + 1] = a.y;
        }
    }
    __syncthreads();

    // write phase: thread t -> batch b = t/16, jj = t%16;
    // ROWS_PB/32 float2 stores per thread at rows 32p + 2jj
    const int b  = t >> 4;
    const int jj = t & 15;
#pragma unroll
    for (int p = 0; p < ROWS_PB / 32; p++) {
        const int rloc = 32 * p + 2 * jj;
        const int og   = o0 + rloc;
        if (og < OUT_F) {
            float2 bv = *(const float2*)&bias[og];
            float2 rv;
            rv.x = tile[rloc + 0][b] + bv.x;
            rv.y = tile[rloc + 1][b] + bv.y;
            *(float2*)&out[(size_t)b * OUT_F + og] = rv;
        }
    }
}

// ---------------------------------------------------------------------------
extern "C" void kernel_launch(void* const* d_in, const int* in_sizes, int n_in,
                              void* d_out, int out_size) {
    const float* x      = (const float*)d_in[0];
    const float* values = (const float*)d_in[1];
    const float* bias   = (const float*)d_in[2];
    const void*  rows   = d_in[3];
    const void*  cols   = d_in[4];
    float* out = (float*)d_out;

    const int nnz      = in_sizes[1];
    const int e_blocks = (nnz + 255) / 256;

    // allow >48KB dynamic smem (idempotent; host-side attr, not an allocation)
    cudaFuncSetAttribute(spmm_kernel, cudaFuncAttributeMaxDynamicSharedMemorySize,
                         SMEM_TOTAL);

    // 1) fused: x transpose (fp32->fp16) + row_ptr scatter
    prep_kernel<<<T_BLOCKS + e_blocks, 256>>>(x, rows, (const int*)cols, nnz);

    // 2) fused gather/accumulate + bias + final write (192 rows/block)
    spmm_kernel<<<SPMM_BLOCKS, 1024, SMEM_TOTAL>>>(cols, values, bias, out, nnz);
}